// round 12
// baseline (speedup 1.0000x reference)
#include <cuda_runtime.h>
#include <cuda_fp16.h>
#include <cstdint>

#define B_ 4
#define M_ 2048
#define D_ 1024
#define N_ 64
#define P_ 32
#define S_ 2048
#define BM_ 8192

// ---------------- scratch (device globals; no allocs allowed) ----------------
__device__ __half g_logits_h[(long)B_ * M_ * S_];   // 32 MB, (b,m,s) fp16

__device__ __half g_xh [(long)BM_ * D_];        // x hi (8192,1024)
__device__ __half g_xTh[(long)B_ * D_ * M_];    // x^T hi per b (1024,2048)
__device__ __half g_pTh[(long)S_ * D_];         // phi^T hi (2048,1024)
__device__ __half g_WTh[(long)N_ * D_ * D_];    // W^T hi per n
__device__ __half g_dTh[(long)B_ * S_ * M_];    // dispatch^T hi (b,s,m)
__device__ __half g_cbh[(long)B_ * M_ * S_];    // combine hi (b,m,s)
__device__ __half g_slh[(long)B_ * S_ * D_];    // slots hi (b,s,d)
__device__ __half g_yTh[(long)B_ * D_ * S_];    // y^T hi per b (1024,2048)

// ---------------- side stream + events (created at static-init time) ----------------
struct StreamPack {
    cudaStream_t s2 = nullptr;
    cudaEvent_t evRoot = nullptr, evXT = nullptr, evW = nullptr,
                ev1 = nullptr, evCb = nullptr;
    bool ok = false;
    StreamPack() {
        ok = (cudaStreamCreateWithFlags(&s2, cudaStreamNonBlocking) == cudaSuccess) &&
             (cudaEventCreateWithFlags(&evRoot, cudaEventDisableTiming) == cudaSuccess) &&
             (cudaEventCreateWithFlags(&evXT,   cudaEventDisableTiming) == cudaSuccess) &&
             (cudaEventCreateWithFlags(&evW,    cudaEventDisableTiming) == cudaSuccess) &&
             (cudaEventCreateWithFlags(&ev1,    cudaEventDisableTiming) == cudaSuccess) &&
             (cudaEventCreateWithFlags(&evCb,   cudaEventDisableTiming) == cudaSuccess);
    }
};
static StreamPack g_sp;

// ---------------- helpers ----------------
__device__ __forceinline__ uint32_t smem_u32(const void* p) {
    uint32_t a;
    asm("{ .reg .u64 t; cvta.to.shared.u64 t, %1; cvt.u32.u64 %0, t; }" : "=r"(a) : "l"(p));
    return a;
}

#define CP16(dst, src) asm volatile("cp.async.cg.shared.global [%0], [%1], 16;" :: "r"(dst), "l"(src))
#define CP_COMMIT()    asm volatile("cp.async.commit_group;" ::: "memory")
#define CP_WAIT1()     asm volatile("cp.async.wait_group 1;" ::: "memory")
#define CP_WAIT0()     asm volatile("cp.async.wait_group 0;" ::: "memory")

__device__ __forceinline__ uint32_t swz(int r, int c) {
    return ((uint32_t)r << 7) + ((uint32_t)((c ^ (r & 7)) & 7) << 4);
}

__device__ __forceinline__ void ldsm_x4(uint32_t addr, uint32_t& r0, uint32_t& r1,
                                        uint32_t& r2, uint32_t& r3) {
    asm volatile("ldmatrix.sync.aligned.m8n8.x4.shared.b16 {%0,%1,%2,%3}, [%4];"
                 : "=r"(r0), "=r"(r1), "=r"(r2), "=r"(r3) : "r"(addr));
}
__device__ __forceinline__ void mma16816(float* c, const uint32_t* a, uint32_t b0, uint32_t b1) {
    asm volatile("mma.sync.aligned.m16n8k16.row.col.f32.f16.f16.f32 "
                 "{%0,%1,%2,%3}, {%4,%5,%6,%7}, {%8,%9}, {%0,%1,%2,%3};"
                 : "+f"(c[0]), "+f"(c[1]), "+f"(c[2]), "+f"(c[3])
                 : "r"(a[0]), "r"(a[1]), "r"(a[2]), "r"(a[3]), "r"(b0), "r"(b1));
}

// ---------------------------------------------------------------------------
// fp16 GEMM via mma.sync, 1-pass, fp32 accum (validated round-11 config).
// 128 threads, 2x2 warp grid, warp tile 64x64, 3-stage cp.async, K-step 64.
// ---------------------------------------------------------------------------
template <int EPI, int GATHER>
__global__ __launch_bounds__(128, 2)
void mma_gemm(const __half* __restrict__ Ah, const __half* __restrict__ Bh,
              float* __restrict__ C, __half* __restrict__ Ch,
              const float* __restrict__ bias,
              int Kdim, int ldC, long strideA, long strideB, long strideC,
              int aZmod)
{
    extern __shared__ char smem[];
    const uint32_t sb = smem_u32(smem);

    constexpr uint32_t TA = 128 * 128;           // 16 KB
    constexpr uint32_t TB = 128 * 128;
    constexpr uint32_t STAGE = TA + TB;          // 32 KB

    const int tid = threadIdx.x, lane = tid & 31, wid = tid >> 5;
    const int warpRow = wid >> 1, warpCol = wid & 1;      // 2x2, tile 64x64
    const int z = blockIdx.z;
    const int zn = z % aZmod;
    const long offA = (long)zn * strideA;
    const long offB = GATHER ? (long)z * P_ * D_ : (long)z * strideB;
    const long offC = (long)z * strideC;
    const int rowBase = blockIdx.y * 128;
    const int colBase = blockIdx.x * 128;

    const __half* aH = Ah + offA + (long)rowBase * Kdim;
    const __half* bH = Bh + offB + (GATHER ? 0 : (long)colBase * Kdim);

    const int nIter = Kdim >> 6;   // K-step 64

    auto load_stage = [&](int it, int buf) {
        const uint32_t s0 = sb + buf * STAGE;
        const long kOff = (long)it * 64;
        #pragma unroll
        for (int t = tid; t < 128 * 8; t += 128) {
            const int r = t >> 3, c = t & 7;
            const uint32_t o = swz(r, c);
            CP16(s0 + o, (const char*)(aH + (long)r * Kdim + kOff + c * 8));
        }
        #pragma unroll
        for (int t = tid; t < 128 * 8; t += 128) {
            const int r = t >> 3, c = t & 7;
            const uint32_t o = swz(r, c);
            long src;
            if (GATHER) src = (long)(r >> 5) * S_ * D_ + (long)(r & 31) * Kdim + kOff + c * 8;
            else        src = (long)r * Kdim + kOff + c * 8;
            CP16(s0 + TA + o, (const char*)(bH + src));
        }
        CP_COMMIT();
    };

    float acc[4][8][4];
    #pragma unroll
    for (int i = 0; i < 4; i++)
        #pragma unroll
        for (int j = 0; j < 8; j++)
            #pragma unroll
            for (int v = 0; v < 4; v++) acc[i][j][v] = 0.f;

    load_stage(0, 0);
    load_stage(1, 1);

    for (int it = 0; it < nIter; ++it) {
        if (it + 2 <= nIter) CP_WAIT1(); else CP_WAIT0();
        __syncthreads();
        if (it + 2 < nIter) load_stage(it + 2, (it + 2) % 3);

        const uint32_t s0 = sb + (it % 3) * STAGE;
        const uint32_t sAh = s0, sBh = s0 + TA;

        #pragma unroll
        for (int ks = 0; ks < 4; ++ks) {
            uint32_t ah[4][4], bh[8][2];

            const int arow = warpRow * 64 + (lane & 15);
            const int achk = ks * 2 + (lane >> 4);
            #pragma unroll
            for (int i = 0; i < 4; i++) {
                const uint32_t o = swz(arow + i * 16, achk);
                ldsm_x4(sAh + o, ah[i][0], ah[i][1], ah[i][2], ah[i][3]);
            }
            {
                const int brow = warpCol * 64 + (lane & 7) + ((lane >> 4) << 3);
                const int bchk = ks * 2 + ((lane >> 3) & 1);
                #pragma unroll
                for (int jj = 0; jj < 4; jj++) {
                    const uint32_t o = swz(brow + jj * 16, bchk);
                    ldsm_x4(sBh + o, bh[2*jj][0], bh[2*jj][1], bh[2*jj+1][0], bh[2*jj+1][1]);
                }
            }

            #pragma unroll
            for (int i = 0; i < 4; i++)
                #pragma unroll
                for (int j = 0; j < 8; j++)
                    mma16816(acc[i][j], ah[i], bh[j][0], bh[j][1]);
        }
    }

    // ---- epilogue ----
    #pragma unroll
    for (int i = 0; i < 4; i++) {
        const int r0 = rowBase + warpRow * 64 + i * 16 + (lane >> 2);
        const int r1 = r0 + 8;
        float bv0 = 0.f, bv1 = 0.f;
        if (GATHER) { bv0 = bias[(long)z * D_ + r0]; bv1 = bias[(long)z * D_ + r1]; }
        #pragma unroll
        for (int j = 0; j < 8; j++) {
            const int cc = colBase + warpCol * 64 + j * 8 + 2 * (lane & 3);
            float v00 = acc[i][j][0], v01 = acc[i][j][1];
            float v10 = acc[i][j][2], v11 = acc[i][j][3];
            if (GATHER) { v00 += bv0; v01 += bv0; v10 += bv1; v11 += bv1; }
            long o0, o1;
            if (GATHER) {
                const int b = cc >> 5;
                o0 = (long)b * D_ * S_ + (long)r0 * S_ + (long)z * P_ + (cc & 31);
                o1 = (long)b * D_ * S_ + (long)r1 * S_ + (long)z * P_ + (cc & 31);
            } else {
                o0 = offC + (long)r0 * ldC + cc;
                o1 = offC + (long)r1 * ldC + cc;
            }
            if (EPI == 0) {
                *(float2*)(C + o0) = make_float2(v00, v01);
                *(float2*)(C + o1) = make_float2(v10, v11);
            } else {
                *(__half2*)(Ch + o0) = __floats2half2_rn(v00, v01);
                *(__half2*)(Ch + o1) = __floats2half2_rn(v10, v11);
            }
        }
    }
}

// ---------------------------------------------------------------------------
// fp32 -> fp16 hi; grid-stride (small fixed grid, low SM footprint)
__global__ __launch_bounds__(256)
void convert_h_kernel(const float* __restrict__ in, __half* __restrict__ oh, long n4)
{
    for (long i4 = (long)blockIdx.x * 256 + threadIdx.x; i4 < n4;
         i4 += (long)gridDim.x * 256) {
        const float4 v = ((const float4*)in)[i4];
        ((__half2*)oh)[i4 * 2]     = __floats2half2_rn(v.x, v.y);
        ((__half2*)oh)[i4 * 2 + 1] = __floats2half2_rn(v.z, v.w);
    }
}

// transpose: in (R, Cc) fp32 -> out (Cc, R) fp16 hi, batched z; grid-stride tiles.
__global__ __launch_bounds__(256)
void transpose_h_kernel(const float* __restrict__ in, __half* __restrict__ oh,
                        int R, int Cc, long sIn, long sOut, int nz)
{
    __shared__ float t[64][33];
    const int tx = threadIdx.x, ty = threadIdx.y;   // 32 x 8
    const int ctiles = Cc / 32, rtiles = R / 64;
    const int ntiles = ctiles * rtiles * nz;

    for (int tile = blockIdx.x; tile < ntiles; tile += gridDim.x) {
        const int zc = tile / (ctiles * rtiles);
        const int rem = tile % (ctiles * rtiles);
        const int c0 = (rem % ctiles) * 32;
        const int r0 = (rem / ctiles) * 64;
        const float* ip = in + (long)zc * sIn;
        __half* op = oh + (long)zc * sOut;

        #pragma unroll
        for (int j = 0; j < 8; j++)
            t[ty + j * 8][tx] = ip[(long)(r0 + ty + j * 8) * Cc + c0 + tx];
        __syncthreads();
        #pragma unroll
        for (int j = 0; j < 4; j++) {
            const int c = ty + j * 8;
            const long o = ((long)(c0 + c) * R + r0 + 2 * tx) >> 1;
            ((__half2*)op)[o] = __floats2half2_rn(t[2 * tx][c], t[2 * tx + 1][c]);
        }
        __syncthreads();
    }
}

// dispatch softmax over batch axis (fp16 logits in) + transposed fp16 write
__global__ __launch_bounds__(1024)
void dispatch_kernel()
{
    __shared__ float t[B_][32][33];
    const int s0 = blockIdx.x * 32, m0 = blockIdx.y * 32;
    const int tx = threadIdx.x, ty = threadIdx.y;
    const long m = m0 + ty, s = s0 + tx;

    float v[B_];
    float mx = -1e30f;
    #pragma unroll
    for (int b = 0; b < B_; b++) {
        v[b] = __half2float(g_logits_h[((long)b * M_ + m) * S_ + s]);
        mx = fmaxf(mx, v[b]);
    }
    float sum = 0.f;
    #pragma unroll
    for (int b = 0; b < B_; b++) { v[b] = __expf(v[b] - mx); sum += v[b]; }
    const float inv = 1.f / sum;
    #pragma unroll
    for (int b = 0; b < B_; b++) t[b][ty][tx] = v[b] * inv;
    __syncthreads();
    const int u = tx & 15;
    #pragma unroll
    for (int bb = 0; bb < 2; bb++) {
        const int b = (tx >> 4) + 2 * bb;
        const long o = (((long)b * S_ + s0 + ty) * M_ + m0 + 2 * u) >> 1;
        ((__half2*)g_dTh)[o] = __floats2half2_rn(t[b][2 * u][ty], t[b][2 * u + 1][ty]);
    }
}

// combine softmax over S per (b,m) row (fp16 logits in, fp16 out)
__global__ __launch_bounds__(256)
void combine_kernel()
{
    const long row = blockIdx.x;
    const __half2* in = (const __half2*)(g_logits_h + row * (long)S_);
    const int tid = threadIdx.x;

    float v[8];
    #pragma unroll
    for (int i = 0; i < 4; i++) {
        const float2 p = __half22float2(in[tid * 4 + i]);
        v[2 * i] = p.x; v[2 * i + 1] = p.y;
    }
    float mx = -1e30f;
    #pragma unroll
    for (int i = 0; i < 8; i++) mx = fmaxf(mx, v[i]);

    __shared__ float sred[8];
    #pragma unroll
    for (int o = 16; o; o >>= 1) mx = fmaxf(mx, __shfl_xor_sync(0xffffffffu, mx, o));
    if ((tid & 31) == 0) sred[tid >> 5] = mx;
    __syncthreads();
    float bmx = sred[0];
    #pragma unroll
    for (int w = 1; w < 8; w++) bmx = fmaxf(bmx, sred[w]);

    float sum = 0.f;
    #pragma unroll
    for (int i = 0; i < 8; i++) { v[i] = __expf(v[i] - bmx); sum += v[i]; }
    #pragma unroll
    for (int o = 16; o; o >>= 1) sum += __shfl_xor_sync(0xffffffffu, sum, o);
    __syncthreads();
    if ((tid & 31) == 0) sred[tid >> 5] = sum;
    __syncthreads();
    float bsum = 0.f;
    #pragma unroll
    for (int w = 0; w < 8; w++) bsum += sred[w];

    const float inv = 1.f / bsum;
    __half2* oh = (__half2*)(g_cbh + row * (long)S_);
    #pragma unroll
    for (int i = 0; i < 4; i++)
        oh[tid * 4 + i] = __floats2half2_rn(v[2 * i] * inv, v[2 * i + 1] * inv);
}

// ---------------------------------------------------------------------------
extern "C" void kernel_launch(void* const* d_in, const int* in_sizes, int n_in,
                              void* d_out, int out_size)
{
    const float* x    = (const float*)d_in[0];   // (B, M, D)
    const float* phi  = (const float*)d_in[1];   // (D, N, P) = (D, S)
    const float* W    = (const float*)d_in[2];   // (N, D, D)
    const float* bias = (const float*)d_in[3];   // (N, D)
    float* out = (float*)d_out;                  // (B, M, D)

    __half *lgh, *xh, *xTh, *pTh, *WTh, *dTh, *cbh, *slh, *yTh;
    cudaGetSymbolAddress((void**)&lgh, g_logits_h);
    cudaGetSymbolAddress((void**)&xh,  g_xh);
    cudaGetSymbolAddress((void**)&xTh, g_xTh);
    cudaGetSymbolAddress((void**)&pTh, g_pTh);
    cudaGetSymbolAddress((void**)&WTh, g_WTh);
    cudaGetSymbolAddress((void**)&dTh, g_dTh);
    cudaGetSymbolAddress((void**)&cbh, g_cbh);
    cudaGetSymbolAddress((void**)&slh, g_slh);
    cudaGetSymbolAddress((void**)&yTh, g_yTh);

    const int SMEM1 = 3 * (128 * 128 + 128 * 128);   // 98304
    cudaFuncSetAttribute(mma_gemm<0, 0>, cudaFuncAttributeMaxDynamicSharedMemorySize, SMEM1);
    cudaFuncSetAttribute(mma_gemm<1, 0>, cudaFuncAttributeMaxDynamicSharedMemorySize, SMEM1);
    cudaFuncSetAttribute(mma_gemm<1, 1>, cudaFuncAttributeMaxDynamicSharedMemorySize, SMEM1);

    const int BIGZ = 1 << 30;
    const int SMALLGRID = 296;   // low-footprint grid: ~2 CTAs/SM of warp slots
    const bool fork = g_sp.ok;
    cudaStream_t s2 = fork ? g_sp.s2 : (cudaStream_t)0;

    // ---- fork side stream: xT transpose, W transpose (needed by GEMM3/4)
    if (fork) {
        cudaEventRecord(g_sp.evRoot, 0);
        cudaStreamWaitEvent(s2, g_sp.evRoot, 0);
    }
    transpose_h_kernel<<<SMALLGRID, dim3(32, 8), 0, s2>>>(
        x, xTh, M_, D_, (long)M_ * D_, (long)D_ * M_, B_);
    if (fork) cudaEventRecord(g_sp.evXT, s2);
    transpose_h_kernel<<<SMALLGRID, dim3(32, 8), 0, s2>>>(
        W, WTh, D_, D_, (long)D_ * D_, (long)D_ * D_, N_);
    if (fork) cudaEventRecord(g_sp.evW, s2);

    // ---- main stream: prep for GEMM1
    convert_h_kernel<<<SMALLGRID, 256>>>(x, xh, (long)(BM_ * D_) / 4);
    transpose_h_kernel<<<SMALLGRID, dim3(32, 8)>>>(
        phi, pTh, D_, S_, 0, 0, 1);

    // 1) logits = x2d @ phi -> fp16 (b,m,s)
    mma_gemm<1, 0><<<dim3(S_ / 128, BM_ / 128, 1), 128, SMEM1>>>(
        xh, pTh, nullptr, lgh, nullptr,
        D_, S_, 0, 0, 0, BIGZ);
    if (fork) cudaEventRecord(g_sp.ev1, 0);

    // 2a) dispatch softmax (main)
    dispatch_kernel<<<dim3(S_ / 32, M_ / 32), dim3(32, 32)>>>();

    // 2b) combine softmax on side stream
    if (fork) {
        cudaStreamWaitEvent(s2, g_sp.ev1, 0);
        combine_kernel<<<BM_, 256, 0, s2>>>();
        cudaEventRecord(g_sp.evCb, s2);
    } else {
        combine_kernel<<<BM_, 256>>>();
    }

    // 3) slots[b] = dispT[b] @ x[b] (1-pass) -> fp16
    if (fork) cudaStreamWaitEvent(0, g_sp.evXT, 0);
    mma_gemm<1, 0><<<dim3(D_ / 128, S_ / 128, B_), 128, SMEM1>>>(
        dTh, xTh, nullptr, slh, nullptr,
        M_, D_, (long)S_ * M_, (long)D_ * M_, (long)S_ * D_, BIGZ);

    // 4) y^T per expert, batched over b (1-pass, gathered B, +bias)
    if (fork) cudaStreamWaitEvent(0, g_sp.evW, 0);
    mma_gemm<1, 1><<<dim3(1, D_ / 128, N_), 128, SMEM1>>>(
        WTh, slh, nullptr, yTh, bias,
        D_, S_, (long)D_ * D_, 0, 0, BIGZ);

    // 5) out[b] = comb[b] @ y[b] (1-pass) -> fp32
    if (fork) cudaStreamWaitEvent(0, g_sp.evCb, 0);
    mma_gemm<0, 0><<<dim3(D_ / 128, M_ / 128, B_), 128, SMEM1>>>(
        cbh, yTh, out, nullptr, nullptr,
        S_, D_, (long)M_ * S_, (long)D_ * S_, (long)M_ * D_, BIGZ);
}

// round 13
// speedup vs baseline: 1.2902x; 1.2902x over previous
#include <cuda_runtime.h>
#include <cuda_fp16.h>
#include <cstdint>

#define B_ 4
#define M_ 2048
#define D_ 1024
#define N_ 64
#define P_ 32
#define S_ 2048
#define BM_ 8192

// ---------------- scratch (device globals; no allocs allowed) ----------------
__device__ __half g_logits_h[(long)B_ * M_ * S_];   // 32 MB, (b,m,s) fp16

__device__ __half g_xh [(long)BM_ * D_];        // x hi (8192,1024)
__device__ __half g_xTh[(long)B_ * D_ * M_];    // x^T hi per b (1024,2048)
__device__ __half g_pTh[(long)S_ * D_];         // phi^T hi (2048,1024)
__device__ __half g_WTh[(long)N_ * D_ * D_];    // W^T hi per n
__device__ __half g_dTh[(long)B_ * S_ * M_];    // dispatch^T hi (b,s,m)
__device__ __half g_cbh[(long)B_ * M_ * S_];    // combine hi (b,m,s)
__device__ __half g_slh[(long)B_ * S_ * D_];    // slots hi (b,s,d)
__device__ __half g_yTh[(long)B_ * D_ * S_];    // y^T hi per b (1024,2048)

// ---------------- side stream + events (created at static-init time) ----------------
struct StreamPack {
    cudaStream_t s2 = nullptr;
    cudaEvent_t evRoot = nullptr, evPhi = nullptr, evXT = nullptr, evW = nullptr,
                ev1 = nullptr, evCb = nullptr;
    bool ok = false;
    StreamPack() {
        ok = (cudaStreamCreateWithFlags(&s2, cudaStreamNonBlocking) == cudaSuccess) &&
             (cudaEventCreateWithFlags(&evRoot, cudaEventDisableTiming) == cudaSuccess) &&
             (cudaEventCreateWithFlags(&evPhi,  cudaEventDisableTiming) == cudaSuccess) &&
             (cudaEventCreateWithFlags(&evXT,   cudaEventDisableTiming) == cudaSuccess) &&
             (cudaEventCreateWithFlags(&evW,    cudaEventDisableTiming) == cudaSuccess) &&
             (cudaEventCreateWithFlags(&ev1,    cudaEventDisableTiming) == cudaSuccess) &&
             (cudaEventCreateWithFlags(&evCb,   cudaEventDisableTiming) == cudaSuccess);
    }
};
static StreamPack g_sp;

// ---------------- helpers ----------------
__device__ __forceinline__ uint32_t smem_u32(const void* p) {
    uint32_t a;
    asm("{ .reg .u64 t; cvta.to.shared.u64 t, %1; cvt.u32.u64 %0, t; }" : "=r"(a) : "l"(p));
    return a;
}

#define CP16(dst, src) asm volatile("cp.async.cg.shared.global [%0], [%1], 16;" :: "r"(dst), "l"(src))
#define CP_COMMIT()    asm volatile("cp.async.commit_group;" ::: "memory")
#define CP_WAIT1()     asm volatile("cp.async.wait_group 1;" ::: "memory")
#define CP_WAIT0()     asm volatile("cp.async.wait_group 0;" ::: "memory")

__device__ __forceinline__ uint32_t swz(int r, int c) {
    return ((uint32_t)r << 7) + ((uint32_t)((c ^ (r & 7)) & 7) << 4);
}

__device__ __forceinline__ void ldsm_x4(uint32_t addr, uint32_t& r0, uint32_t& r1,
                                        uint32_t& r2, uint32_t& r3) {
    asm volatile("ldmatrix.sync.aligned.m8n8.x4.shared.b16 {%0,%1,%2,%3}, [%4];"
                 : "=r"(r0), "=r"(r1), "=r"(r2), "=r"(r3) : "r"(addr));
}
__device__ __forceinline__ void mma16816(float* c, const uint32_t* a, uint32_t b0, uint32_t b1) {
    asm volatile("mma.sync.aligned.m16n8k16.row.col.f32.f16.f16.f32 "
                 "{%0,%1,%2,%3}, {%4,%5,%6,%7}, {%8,%9}, {%0,%1,%2,%3};"
                 : "+f"(c[0]), "+f"(c[1]), "+f"(c[2]), "+f"(c[3])
                 : "r"(a[0]), "r"(a[1]), "r"(a[2]), "r"(a[3]), "r"(b0), "r"(b1));
}

// ---------------------------------------------------------------------------
// fp16 GEMM via mma.sync, 1-pass, fp32 accum (validated round-11 config).
// 128 threads, 2x2 warp grid, warp tile 64x64, 3-stage cp.async, K-step 64.
// 2 CTAs/SM (96 KB smem each). EPI: 0 = fp32 store, 1 = fp16 store.
// GATHER=1: expert mode (gathered B rows, bias add, scattered C into yT[b]).
// ---------------------------------------------------------------------------
template <int EPI, int GATHER>
__global__ __launch_bounds__(128, 2)
void mma_gemm(const __half* __restrict__ Ah, const __half* __restrict__ Bh,
              float* __restrict__ C, __half* __restrict__ Ch,
              const float* __restrict__ bias,
              int Kdim, int ldC, long strideA, long strideB, long strideC,
              int aZmod)
{
    extern __shared__ char smem[];
    const uint32_t sb = smem_u32(smem);

    constexpr uint32_t TA = 128 * 128;           // 16 KB
    constexpr uint32_t TB = 128 * 128;
    constexpr uint32_t STAGE = TA + TB;          // 32 KB

    const int tid = threadIdx.x, lane = tid & 31, wid = tid >> 5;
    const int warpRow = wid >> 1, warpCol = wid & 1;      // 2x2, tile 64x64
    const int z = blockIdx.z;
    const int zn = z % aZmod;
    const long offA = (long)zn * strideA;
    const long offB = GATHER ? (long)z * P_ * D_ : (long)z * strideB;
    const long offC = (long)z * strideC;
    const int rowBase = blockIdx.y * 128;
    const int colBase = blockIdx.x * 128;

    const __half* aH = Ah + offA + (long)rowBase * Kdim;
    const __half* bH = Bh + offB + (GATHER ? 0 : (long)colBase * Kdim);

    const int nIter = Kdim >> 6;   // K-step 64

    auto load_stage = [&](int it, int buf) {
        const uint32_t s0 = sb + buf * STAGE;
        const long kOff = (long)it * 64;
        #pragma unroll
        for (int t = tid; t < 128 * 8; t += 128) {
            const int r = t >> 3, c = t & 7;
            const uint32_t o = swz(r, c);
            CP16(s0 + o, (const char*)(aH + (long)r * Kdim + kOff + c * 8));
        }
        #pragma unroll
        for (int t = tid; t < 128 * 8; t += 128) {
            const int r = t >> 3, c = t & 7;
            const uint32_t o = swz(r, c);
            long src;
            if (GATHER) src = (long)(r >> 5) * S_ * D_ + (long)(r & 31) * Kdim + kOff + c * 8;
            else        src = (long)r * Kdim + kOff + c * 8;
            CP16(s0 + TA + o, (const char*)(bH + src));
        }
        CP_COMMIT();
    };

    float acc[4][8][4];
    #pragma unroll
    for (int i = 0; i < 4; i++)
        #pragma unroll
        for (int j = 0; j < 8; j++)
            #pragma unroll
            for (int v = 0; v < 4; v++) acc[i][j][v] = 0.f;

    load_stage(0, 0);
    load_stage(1, 1);

    for (int it = 0; it < nIter; ++it) {
        if (it + 2 <= nIter) CP_WAIT1(); else CP_WAIT0();
        __syncthreads();
        if (it + 2 < nIter) load_stage(it + 2, (it + 2) % 3);

        const uint32_t s0 = sb + (it % 3) * STAGE;
        const uint32_t sAh = s0, sBh = s0 + TA;

        #pragma unroll
        for (int ks = 0; ks < 4; ++ks) {
            uint32_t ah[4][4], bh[8][2];

            const int arow = warpRow * 64 + (lane & 15);
            const int achk = ks * 2 + (lane >> 4);
            #pragma unroll
            for (int i = 0; i < 4; i++) {
                const uint32_t o = swz(arow + i * 16, achk);
                ldsm_x4(sAh + o, ah[i][0], ah[i][1], ah[i][2], ah[i][3]);
            }
            {
                const int brow = warpCol * 64 + (lane & 7) + ((lane >> 4) << 3);
                const int bchk = ks * 2 + ((lane >> 3) & 1);
                #pragma unroll
                for (int jj = 0; jj < 4; jj++) {
                    const uint32_t o = swz(brow + jj * 16, bchk);
                    ldsm_x4(sBh + o, bh[2*jj][0], bh[2*jj][1], bh[2*jj+1][0], bh[2*jj+1][1]);
                }
            }

            #pragma unroll
            for (int i = 0; i < 4; i++)
                #pragma unroll
                for (int j = 0; j < 8; j++)
                    mma16816(acc[i][j], ah[i], bh[j][0], bh[j][1]);
        }
    }

    // ---- epilogue ----
    #pragma unroll
    for (int i = 0; i < 4; i++) {
        const int r0 = rowBase + warpRow * 64 + i * 16 + (lane >> 2);
        const int r1 = r0 + 8;
        float bv0 = 0.f, bv1 = 0.f;
        if (GATHER) { bv0 = bias[(long)z * D_ + r0]; bv1 = bias[(long)z * D_ + r1]; }
        #pragma unroll
        for (int j = 0; j < 8; j++) {
            const int cc = colBase + warpCol * 64 + j * 8 + 2 * (lane & 3);
            float v00 = acc[i][j][0], v01 = acc[i][j][1];
            float v10 = acc[i][j][2], v11 = acc[i][j][3];
            if (GATHER) { v00 += bv0; v01 += bv0; v10 += bv1; v11 += bv1; }
            long o0, o1;
            if (GATHER) {
                const int b = cc >> 5;
                o0 = (long)b * D_ * S_ + (long)r0 * S_ + (long)z * P_ + (cc & 31);
                o1 = (long)b * D_ * S_ + (long)r1 * S_ + (long)z * P_ + (cc & 31);
            } else {
                o0 = offC + (long)r0 * ldC + cc;
                o1 = offC + (long)r1 * ldC + cc;
            }
            if (EPI == 0) {
                *(float2*)(C + o0) = make_float2(v00, v01);
                *(float2*)(C + o1) = make_float2(v10, v11);
            } else {
                *(__half2*)(Ch + o0) = __floats2half2_rn(v00, v01);
                *(__half2*)(Ch + o1) = __floats2half2_rn(v10, v11);
            }
        }
    }
}

// ---------------------------------------------------------------------------
// fp32 -> fp16 hi; float4 in, 2x half2 out (full grid — round-11 config)
__global__ __launch_bounds__(256)
void convert_h_kernel(const float* __restrict__ in, __half* __restrict__ oh)
{
    const long i4 = (long)blockIdx.x * 256 + threadIdx.x;
    const float4 v = ((const float4*)in)[i4];
    ((__half2*)oh)[i4 * 2]     = __floats2half2_rn(v.x, v.y);
    ((__half2*)oh)[i4 * 2 + 1] = __floats2half2_rn(v.z, v.w);
}

// transpose: in (R, Cc) fp32 -> out (Cc, R) fp16 hi, batched z (full grid).
__global__ __launch_bounds__(256)
void transpose_h_kernel(const float* __restrict__ in, __half* __restrict__ oh,
                        int R, int Cc, long sIn, long sOut)
{
    in += (long)blockIdx.z * sIn;
    oh += (long)blockIdx.z * sOut;
    __shared__ float t[64][33];
    const int c0 = blockIdx.x * 32, r0 = blockIdx.y * 64;
    const int tx = threadIdx.x, ty = threadIdx.y;   // 32 x 8
    #pragma unroll
    for (int j = 0; j < 8; j++)
        t[ty + j * 8][tx] = in[(long)(r0 + ty + j * 8) * Cc + c0 + tx];
    __syncthreads();
    #pragma unroll
    for (int j = 0; j < 4; j++) {
        const int c = ty + j * 8;
        const long o = ((long)(c0 + c) * R + r0 + 2 * tx) >> 1;
        ((__half2*)oh)[o] = __floats2half2_rn(t[2 * tx][c], t[2 * tx + 1][c]);
    }
}

// dispatch softmax over batch axis (fp16 logits in) + transposed fp16 write
__global__ __launch_bounds__(1024)
void dispatch_kernel()
{
    __shared__ float t[B_][32][33];
    const int s0 = blockIdx.x * 32, m0 = blockIdx.y * 32;
    const int tx = threadIdx.x, ty = threadIdx.y;
    const long m = m0 + ty, s = s0 + tx;

    float v[B_];
    float mx = -1e30f;
    #pragma unroll
    for (int b = 0; b < B_; b++) {
        v[b] = __half2float(g_logits_h[((long)b * M_ + m) * S_ + s]);
        mx = fmaxf(mx, v[b]);
    }
    float sum = 0.f;
    #pragma unroll
    for (int b = 0; b < B_; b++) { v[b] = __expf(v[b] - mx); sum += v[b]; }
    const float inv = 1.f / sum;
    #pragma unroll
    for (int b = 0; b < B_; b++) t[b][ty][tx] = v[b] * inv;
    __syncthreads();
    const int u = tx & 15;
    #pragma unroll
    for (int bb = 0; bb < 2; bb++) {
        const int b = (tx >> 4) + 2 * bb;
        const long o = (((long)b * S_ + s0 + ty) * M_ + m0 + 2 * u) >> 1;
        ((__half2*)g_dTh)[o] = __floats2half2_rn(t[b][2 * u][ty], t[b][2 * u + 1][ty]);
    }
}

// combine softmax over S per (b,m) row (fp16 logits in, fp16 out)
__global__ __launch_bounds__(256)
void combine_kernel()
{
    const long row = blockIdx.x;
    const __half2* in = (const __half2*)(g_logits_h + row * (long)S_);
    const int tid = threadIdx.x;

    float v[8];
    #pragma unroll
    for (int i = 0; i < 4; i++) {
        const float2 p = __half22float2(in[tid * 4 + i]);
        v[2 * i] = p.x; v[2 * i + 1] = p.y;
    }
    float mx = -1e30f;
    #pragma unroll
    for (int i = 0; i < 8; i++) mx = fmaxf(mx, v[i]);

    __shared__ float sred[8];
    #pragma unroll
    for (int o = 16; o; o >>= 1) mx = fmaxf(mx, __shfl_xor_sync(0xffffffffu, mx, o));
    if ((tid & 31) == 0) sred[tid >> 5] = mx;
    __syncthreads();
    float bmx = sred[0];
    #pragma unroll
    for (int w = 1; w < 8; w++) bmx = fmaxf(bmx, sred[w]);

    float sum = 0.f;
    #pragma unroll
    for (int i = 0; i < 8; i++) { v[i] = __expf(v[i] - bmx); sum += v[i]; }
    #pragma unroll
    for (int o = 16; o; o >>= 1) sum += __shfl_xor_sync(0xffffffffu, sum, o);
    __syncthreads();
    if ((tid & 31) == 0) sred[tid >> 5] = sum;
    __syncthreads();
    float bsum = 0.f;
    #pragma unroll
    for (int w = 0; w < 8; w++) bsum += sred[w];

    const float inv = 1.f / bsum;
    __half2* oh = (__half2*)(g_cbh + row * (long)S_);
    #pragma unroll
    for (int i = 0; i < 4; i++)
        oh[tid * 4 + i] = __floats2half2_rn(v[2 * i] * inv, v[2 * i + 1] * inv);
}

// ---------------------------------------------------------------------------
extern "C" void kernel_launch(void* const* d_in, const int* in_sizes, int n_in,
                              void* d_out, int out_size)
{
    const float* x    = (const float*)d_in[0];   // (B, M, D)
    const float* phi  = (const float*)d_in[1];   // (D, N, P) = (D, S)
    const float* W    = (const float*)d_in[2];   // (N, D, D)
    const float* bias = (const float*)d_in[3];   // (N, D)
    float* out = (float*)d_out;                  // (B, M, D)

    __half *lgh, *xh, *xTh, *pTh, *WTh, *dTh, *cbh, *slh, *yTh;
    cudaGetSymbolAddress((void**)&lgh, g_logits_h);
    cudaGetSymbolAddress((void**)&xh,  g_xh);
    cudaGetSymbolAddress((void**)&xTh, g_xTh);
    cudaGetSymbolAddress((void**)&pTh, g_pTh);
    cudaGetSymbolAddress((void**)&WTh, g_WTh);
    cudaGetSymbolAddress((void**)&dTh, g_dTh);
    cudaGetSymbolAddress((void**)&cbh, g_cbh);
    cudaGetSymbolAddress((void**)&slh, g_slh);
    cudaGetSymbolAddress((void**)&yTh, g_yTh);

    const int SMEM1 = 3 * (128 * 128 + 128 * 128);   // 98304
    cudaFuncSetAttribute(mma_gemm<0, 0>, cudaFuncAttributeMaxDynamicSharedMemorySize, SMEM1);
    cudaFuncSetAttribute(mma_gemm<1, 0>, cudaFuncAttributeMaxDynamicSharedMemorySize, SMEM1);
    cudaFuncSetAttribute(mma_gemm<1, 1>, cudaFuncAttributeMaxDynamicSharedMemorySize, SMEM1);

    const int BIGZ = 1 << 30;
    const bool fork = g_sp.ok;
    cudaStream_t s2 = fork ? g_sp.s2 : (cudaStream_t)0;

    // ---- fork side stream: phi transpose (GEMM1 dep), xT, W transposes
    if (fork) {
        cudaEventRecord(g_sp.evRoot, 0);
        cudaStreamWaitEvent(s2, g_sp.evRoot, 0);
    }
    transpose_h_kernel<<<dim3(S_ / 32, D_ / 64, 1), dim3(32, 8), 0, s2>>>(
        phi, pTh, D_, S_, 0, 0);
    if (fork) cudaEventRecord(g_sp.evPhi, s2);
    transpose_h_kernel<<<dim3(D_ / 32, M_ / 64, B_), dim3(32, 8), 0, s2>>>(
        x, xTh, M_, D_, (long)M_ * D_, (long)D_ * M_);
    if (fork) cudaEventRecord(g_sp.evXT, s2);
    transpose_h_kernel<<<dim3(D_ / 32, D_ / 64, N_), dim3(32, 8), 0, s2>>>(
        W, WTh, D_, D_, (long)D_ * D_, (long)D_ * D_);
    if (fork) cudaEventRecord(g_sp.evW, s2);

    // ---- main stream: convert x for GEMM1
    convert_h_kernel<<<(BM_ * D_) / 1024, 256>>>(x, xh);

    // 1) logits = x2d @ phi -> fp16 (b,m,s)
    if (fork) cudaStreamWaitEvent(0, g_sp.evPhi, 0);
    mma_gemm<1, 0><<<dim3(S_ / 128, BM_ / 128, 1), 128, SMEM1>>>(
        xh, pTh, nullptr, lgh, nullptr,
        D_, S_, 0, 0, 0, BIGZ);
    if (fork) cudaEventRecord(g_sp.ev1, 0);

    // 2a) dispatch softmax (main)
    dispatch_kernel<<<dim3(S_ / 32, M_ / 32), dim3(32, 32)>>>();

    // 2b) combine softmax on side stream
    if (fork) {
        cudaStreamWaitEvent(s2, g_sp.ev1, 0);
        combine_kernel<<<BM_, 256, 0, s2>>>();
        cudaEventRecord(g_sp.evCb, s2);
    } else {
        combine_kernel<<<BM_, 256>>>();
    }

    // 3) slots[b] = dispT[b] @ x[b] (1-pass) -> fp16
    if (fork) cudaStreamWaitEvent(0, g_sp.evXT, 0);
    mma_gemm<1, 0><<<dim3(D_ / 128, S_ / 128, B_), 128, SMEM1>>>(
        dTh, xTh, nullptr, slh, nullptr,
        M_, D_, (long)S_ * M_, (long)D_ * M_, (long)S_ * D_, BIGZ);

    // 4) y^T per expert, batched over b (1-pass, gathered B, +bias)
    if (fork) cudaStreamWaitEvent(0, g_sp.evW, 0);
    mma_gemm<1, 1><<<dim3(1, D_ / 128, N_), 128, SMEM1>>>(
        WTh, slh, nullptr, yTh, bias,
        D_, S_, (long)D_ * D_, 0, 0, BIGZ);

    // 5) out[b] = comb[b] @ y[b] (1-pass) -> fp32
    if (fork) cudaStreamWaitEvent(0, g_sp.evCb, 0);
    mma_gemm<0, 0><<<dim3(D_ / 128, M_ / 128, B_), 128, SMEM1>>>(
        cbh, yTh, out, nullptr, nullptr,
        S_, D_, (long)M_ * S_, (long)D_ * S_, (long)M_ * D_, BIGZ);
}